// round 13
// baseline (speedup 1.0000x reference)
#include <cuda_runtime.h>
#include <cstddef>
#include <cstdint>

// TMA-bulk staged FWHT. Each CTA double-buffers 8-row (32KB) stages loaded
// with a single cp.async.bulk (UBLKCP) -- one instruction keeps 32KB in
// flight per buffer, 64KB/SM, removing the per-thread LDG scoreboard limit
// that pinned R5-R12 at 67-75% DRAM. Loads bypass L1 (TMA -> SMEM direct).
// Compute per row = R12 champion body: packed f32x2 butterflies,
// stride-33 padded transpose, packed register-resident scale/shift.
//
// Math: thread owns 32 elements i = 128k+4lane+b as v[c], c=4k+b.
// FWHT1024 = FWHT32 over c-bits (i bits 0,1,7,8,9)
//          o FWHT32 over lane-bits (i bits 2..6) via padded-SMEM transpose.

#define NWARPS 8
#define ROWS_PER_STAGE 8
#define STAGE_FLOATS (ROWS_PER_STAGE * 1024)          // 8192 floats = 32KB
#define SCRATCH_FLOATS (NWARPS * 1056)                // 8448 floats
#define MBAR_FLOAT_OFF (2 * STAGE_FLOATS + SCRATCH_FLOATS)   // 24832
#define SMEM_BYTES (MBAR_FLOAT_OFF * 4 + 16)          // 99344 B

__device__ __forceinline__ unsigned long long pk2(float lo, float hi)
{
    unsigned long long r;
    asm("mov.b64 %0, {%1, %2};" : "=l"(r) : "f"(lo), "f"(hi));
    return r;
}
__device__ __forceinline__ void upk2(float& lo, float& hi, unsigned long long p)
{
    asm("mov.b64 {%0, %1}, %2;" : "=f"(lo), "=f"(hi) : "l"(p));
}
__device__ __forceinline__ void pbfly(float* v, int i, int j)
{
    unsigned long long A = pk2(v[2*i], v[2*i+1]);
    unsigned long long B = pk2(v[2*j], v[2*j+1]);
    unsigned long long S, D;
    asm("add.rn.f32x2 %0, %1, %2;" : "=l"(S) : "l"(A), "l"(B));
    asm("sub.rn.f32x2 %0, %1, %2;" : "=l"(D) : "l"(A), "l"(B));
    upk2(v[2*i], v[2*i+1], S);
    upk2(v[2*j], v[2*j+1], D);
}
__device__ __forceinline__ void fwht32(float* v)
{
    #pragma unroll
    for (int q = 0; q < 16; q++) {              // stage m=1: scalar
        float u = v[2*q], w = v[2*q+1];
        v[2*q] = u + w;  v[2*q+1] = u - w;
    }
    #pragma unroll
    for (int mq = 1; mq < 16; mq <<= 1) {       // m=2,4,8,16: packed
        #pragma unroll
        for (int q = 0; q < 16; q++)
            if ((q & mq) == 0) pbfly(v, q, q | mq);
    }
}

__device__ __forceinline__ void mbar_expect_tx(uint32_t mbar, uint32_t bytes)
{
    asm volatile("mbarrier.arrive.expect_tx.shared::cta.b64 _, [%0], %1;"
                 :: "r"(mbar), "r"(bytes) : "memory");
}
__device__ __forceinline__ void bulk_g2s(uint32_t smem_dst, const void* gmem_src,
                                         uint32_t bytes, uint32_t mbar)
{
    asm volatile("cp.async.bulk.shared::cta.global.mbarrier::complete_tx::bytes "
                 "[%0], [%1], %2, [%3];"
                 :: "r"(smem_dst), "l"(gmem_src), "r"(bytes), "r"(mbar)
                 : "memory");
}
__device__ __forceinline__ void mbar_wait(uint32_t mbar, uint32_t parity)
{
    uint32_t done;
    do {
        asm volatile("{\n\t.reg .pred p;\n\t"
                     "mbarrier.try_wait.parity.acquire.cta.shared::cta.b64 p, [%1], %2, 0x989680;\n\t"
                     "selp.b32 %0, 1, 0, p;\n\t}"
                     : "=r"(done) : "r"(mbar), "r"(parity) : "memory");
    } while (!done);
}

__global__ void __launch_bounds__(256, 2)
fwht1024_kernel(const float* __restrict__ x,
                const float* __restrict__ scale,
                const float* __restrict__ shift,
                float* __restrict__ out,
                int nrows, int nstages, int stage_stride)
{
    extern __shared__ float smem[];
    const int tid    = threadIdx.x;
    const int wlocal = tid >> 5;
    const int lane   = tid & 31;

    float* __restrict__ stg0 = smem;
    float* __restrict__ stg1 = smem + STAGE_FLOATS;
    float* __restrict__ sm   = smem + 2 * STAGE_FLOATS + wlocal * 1056;
    const uint32_t mbar_base =
        (uint32_t)__cvta_generic_to_shared(smem + MBAR_FLOAT_OFF);
    const uint32_t mb0 = mbar_base, mb1 = mbar_base + 8;

    float4* __restrict__ xo4 = reinterpret_cast<float4*>(out);

    // ---- packed register-resident scale*(1/32) and shift ----
    unsigned long long spp[16], sbp[16];
    {
        const float4* __restrict__ sc4 = reinterpret_cast<const float4*>(scale);
        const float4* __restrict__ sh4 = reinterpret_cast<const float4*>(shift);
        const float inv = 0.03125f;           // 1/sqrt(1024)
        #pragma unroll
        for (int k = 0; k < 8; k++) {
            float4 s4 = __ldg(&sc4[k * 32 + lane]);
            float4 h4 = __ldg(&sh4[k * 32 + lane]);
            spp[2*k+0] = pk2(s4.x * inv, s4.y * inv);
            spp[2*k+1] = pk2(s4.z * inv, s4.w * inv);
            sbp[2*k+0] = pk2(h4.x, h4.y);
            sbp[2*k+1] = pk2(h4.z, h4.w);
        }
    }

    if (tid == 0) {
        asm volatile("mbarrier.init.shared::cta.b64 [%0], 1;" :: "r"(mb0) : "memory");
        asm volatile("mbarrier.init.shared::cta.b64 [%0], 1;" :: "r"(mb1) : "memory");
    }
    __syncthreads();

    int stage = blockIdx.x;

    // ---- prologue: bulk-load first stage into buffer 0 ----
    if (tid == 0 && stage < nstages) {
        const int base = stage * ROWS_PER_STAGE;
        const uint32_t bytes =
            (uint32_t)min(ROWS_PER_STAGE, nrows - base) * 4096u;
        mbar_expect_tx(mb0, bytes);
        bulk_g2s((uint32_t)__cvta_generic_to_shared(stg0),
                 x + (size_t)base * 1024u, bytes, mb0);
    }

    int ph0 = 0, ph1 = 0;
    int it = 0;
    for (; stage < nstages; stage += stage_stride, it++) {
        const int cur = it & 1;
        float* __restrict__ sbuf = cur ? stg1 : stg0;

        // ---- prefetch next stage into the other buffer (consumed last iter) --
        const int nstage = stage + stage_stride;
        if (tid == 0 && nstage < nstages) {
            const int nbase = nstage * ROWS_PER_STAGE;
            const uint32_t nbytes =
                (uint32_t)min(ROWS_PER_STAGE, nrows - nbase) * 4096u;
            const uint32_t mb = cur ? mb0 : mb1;
            float* dst = cur ? stg0 : stg1;
            mbar_expect_tx(mb, nbytes);
            bulk_g2s((uint32_t)__cvta_generic_to_shared(dst),
                     x + (size_t)nbase * 1024u, nbytes, mb);
        }

        // ---- wait for current stage ----
        if (cur == 0) { mbar_wait(mb0, ph0); ph0 ^= 1; }
        else          { mbar_wait(mb1, ph1); ph1 ^= 1; }

        const int row = stage * ROWS_PER_STAGE + wlocal;
        if (row < nrows) {
            // ---- unpack from linear SMEM (conflict-free LDS.128) ----
            float v[32];
            const float4* __restrict__ r4 =
                reinterpret_cast<const float4*>(sbuf + wlocal * 1024);
            #pragma unroll
            for (int k = 0; k < 8; k++) {
                float4 t = r4[k * 32 + lane];
                v[4*k+0] = t.x; v[4*k+1] = t.y;
                v[4*k+2] = t.z; v[4*k+3] = t.w;
            }

            fwht32(v);                       // bits 0,1,7,8,9

            #pragma unroll
            for (int c = 0; c < 32; c++) sm[lane * 33 + c] = v[c];
            __syncwarp();
            #pragma unroll
            for (int j = 0; j < 32; j++) v[j] = sm[j * 33 + lane];

            fwht32(v);                       // bits 2..6

            #pragma unroll
            for (int j = 0; j < 32; j++) sm[j * 33 + lane] = v[j];
            __syncwarp();
            #pragma unroll
            for (int c = 0; c < 32; c++) v[c] = sm[lane * 33 + c];

            // ---- packed fma epilogue + streaming store ----
            float4* __restrict__ po = xo4 + (size_t)row * 256u;
            #pragma unroll
            for (int k = 0; k < 8; k++) {
                unsigned long long a01 = pk2(v[4*k+0], v[4*k+1]);
                unsigned long long a23 = pk2(v[4*k+2], v[4*k+3]);
                unsigned long long r01, r23;
                asm("fma.rn.f32x2 %0, %1, %2, %3;"
                    : "=l"(r01) : "l"(a01), "l"(spp[2*k+0]), "l"(sbp[2*k+0]));
                asm("fma.rn.f32x2 %0, %1, %2, %3;"
                    : "=l"(r23) : "l"(a23), "l"(spp[2*k+1]), "l"(sbp[2*k+1]));
                float4 r;
                upk2(r.x, r.y, r01);
                upk2(r.z, r.w, r23);
                __stcs(&po[k * 32 + lane], r);
            }
        }

        // all warps done reading sbuf before it is refilled next iteration
        __syncthreads();
    }
}

extern "C" void kernel_launch(void* const* d_in, const int* in_sizes, int n_in,
                              void* d_out, int out_size)
{
    const float* x     = (const float*)d_in[0];
    const float* scale = (const float*)d_in[1];
    const float* shift = (const float*)d_in[2];
    float* out = (float*)d_out;

    const int nrows   = in_sizes[0] / 1024;
    const int nstages = (nrows + ROWS_PER_STAGE - 1) / ROWS_PER_STAGE;

    int sms = 148;
    cudaDeviceGetAttribute(&sms, cudaDevAttrMultiProcessorCount, 0);

    cudaFuncSetAttribute(fwht1024_kernel,
                         cudaFuncAttributeMaxDynamicSharedMemorySize,
                         SMEM_BYTES);

    const int blocks = sms * 2;              // 2 CTAs/SM (99.3KB smem each)
    fwht1024_kernel<<<blocks, 32 * NWARPS, SMEM_BYTES>>>(x, scale, shift, out,
                                                         nrows, nstages, blocks);
}